// round 16
// baseline (speedup 1.0000x reference)
#include <cuda_runtime.h>
#include <cstdint>

#define MAXN 50000
#define MAXE 600064
#define F 128
#define LN_EPS 1e-5f

// ---------------- scratch (device globals; no allocation allowed) ----------
__device__ int   g_src[MAXE];
__device__ int   g_dst[MAXE];
__device__ float g_dinv[MAXN];
__device__ int   g_degi[MAXN];
__device__ int   g_off[MAXN + 1];
__device__ int   g_cur[MAXN];
__device__ int2  g_ew[MAXE];        // packed {src, weight bits}
__device__ float g_h[MAXN * F];     // GEMM1 output (gather1 input)
__device__ float g_h3[MAXN * F];    // GEMM2 output (gather2 input)
__device__ float g_xhi[MAXN * F];   // tf32 hi split of current GEMM input
__device__ float g_xlo[MAXN * F];   // tf32 lo split
__device__ float g_h2hi[MAXN * F];  // gather1 output, split
__device__ float g_h2lo[MAXN * F];
__device__ float g_w1hi[F * F];     // W^T splits: [n][k]
__device__ float g_w1lo[F * F];
__device__ float g_w2hi[F * F];
__device__ float g_w2lo[F * F];
__device__ int   g_bsum[16];

// ---------------- helpers ----------------------------------------------------
__device__ __forceinline__ float tf32f(float x) {
    uint32_t u; asm("cvt.rna.tf32.f32 %0, %1;" : "=r"(u) : "f"(x));
    return __uint_as_float(u);
}

__device__ __forceinline__ void mma_tf32(float c[4],
        uint32_t a0, uint32_t a1, uint32_t a2, uint32_t a3,
        uint32_t b0, uint32_t b1) {
    asm volatile(
        "mma.sync.aligned.m16n8k8.row.col.f32.tf32.tf32.f32 "
        "{%0,%1,%2,%3}, {%4,%5,%6,%7}, {%8,%9}, {%0,%1,%2,%3};"
        : "+f"(c[0]), "+f"(c[1]), "+f"(c[2]), "+f"(c[3])
        : "r"(a0), "r"(a1), "r"(a2), "r"(a3), "r"(b0), "r"(b1));
}

// -------- convert edges (dtype-probing) + degree count ----------------------
__global__ void k_convert_count(const void* __restrict__ ei_raw, int N, int E) {
    __shared__ int s_is64;
    if (threadIdx.x == 0) {
        const unsigned long long* p = (const unsigned long long*)ei_raw;
        unsigned long long mx = 0;
#pragma unroll
        for (int i = 0; i < 32; i++) mx = mx > p[i] ? mx : p[i];
        s_is64 = (mx < (unsigned long long)N);
    }
    __syncthreads();
    int e = blockIdx.x * blockDim.x + threadIdx.x;
    if (e >= E) return;
    int s, d;
    if (s_is64) {
        const long long* p = (const long long*)ei_raw;
        s = (int)p[e]; d = (int)p[E + e];
    } else {
        const int* p = (const int*)ei_raw;
        s = p[e]; d = p[E + e];
    }
    g_src[e] = s;
    g_dst[e] = d;
    atomicAdd(&g_degi[d], 1);
}

// ---------------- scan phase 1: per-block exclusive scan (4096/block) -------
__global__ void __launch_bounds__(1024)
k_scan1(int n) {
    __shared__ int sh[32];
    const int lane = threadIdx.x & 31;
    const int wid  = threadIdx.x >> 5;
    const int i0 = blockIdx.x * 4096 + threadIdx.x * 4;

    int v0 = (i0 + 0 < n) ? g_degi[i0 + 0] : 0;
    int v1 = (i0 + 1 < n) ? g_degi[i0 + 1] : 0;
    int v2 = (i0 + 2 < n) ? g_degi[i0 + 2] : 0;
    int v3 = (i0 + 3 < n) ? g_degi[i0 + 3] : 0;
    int s = v0 + v1 + v2 + v3;

    int x = s;
#pragma unroll
    for (int o = 1; o < 32; o <<= 1) {
        int y = __shfl_up_sync(0xffffffffu, x, o);
        if (lane >= o) x += y;
    }
    if (lane == 31) sh[wid] = x;
    __syncthreads();
    if (wid == 0) {
        int t = sh[lane];
#pragma unroll
        for (int o = 1; o < 32; o <<= 1) {
            int y = __shfl_up_sync(0xffffffffu, t, o);
            if (lane >= o) t += y;
        }
        sh[lane] = t;
    }
    __syncthreads();
    int excl = x - s + ((wid == 0) ? 0 : sh[wid - 1]);

    if (i0 + 0 < n) g_off[i0 + 0] = excl;
    if (i0 + 1 < n) g_off[i0 + 1] = excl + v0;
    if (i0 + 2 < n) g_off[i0 + 2] = excl + v0 + v1;
    if (i0 + 3 < n) g_off[i0 + 3] = excl + v0 + v1 + v2;
    if (threadIdx.x == 1023) g_bsum[blockIdx.x] = excl + s;
}

// ------- scan phase 2 (fused): add block offsets, init cur & dinv ------------
__global__ void k_scan3(int n, int nblk) {
    __shared__ int s_boff;
    int grp = (blockIdx.x * blockDim.x) >> 12;
    if (threadIdx.x == 0) {
        int s = 0;
        for (int b = 0; b < grp; b++) s += g_bsum[b];
        s_boff = s;
    }
    __syncthreads();
    int i = blockIdx.x * blockDim.x + threadIdx.x;
    if (i < n) {
        int val = g_off[i] + s_boff;
        g_off[i] = val;
        g_cur[i] = val;
        g_dinv[i] = rsqrtf((float)g_degi[i] + 1.0f);
    }
    if (blockIdx.x == 0 && threadIdx.x == 0) {
        int s = 0;
        for (int b = 0; b < nblk; b++) s += g_bsum[b];
        g_off[n] = s;
    }
}

__global__ void k_fill(int E) {
    int e = blockIdx.x * blockDim.x + threadIdx.x;
    if (e >= E) return;
    int s = g_src[e];
    int d = g_dst[e];
    int pos = atomicAdd(&g_cur[d], 1);
    float w = g_dinv[s] * g_dinv[d];
    g_ew[pos] = make_int2(s, __float_as_int(w));
}

// ---------------- tf32 split of W1,W2 into transposed [n][k] ----------------
__global__ void k_split_w(const float* __restrict__ W1,
                          const float* __restrict__ W2) {
    int idx = blockIdx.x * blockDim.x + threadIdx.x;
    if (idx >= 2 * F * F) return;
    int sel = idx >> 14;               // F*F == 16384
    int j   = idx & (F * F - 1);
    int k = j >> 7, n = j & 127;
    float w  = sel ? W2[j] : W1[j];
    float hi = tf32f(w);
    float lo = tf32f(w - hi);
    if (sel) { g_w2hi[n * F + k] = hi; g_w2lo[n * F + k] = lo; }
    else     { g_w1hi[n * F + k] = hi; g_w1lo[n * F + k] = lo; }
}

// ---------------- tf32 split of X (row-major) --------------------------------
__global__ void k_split_x(const float* __restrict__ X, int N) {
    int idx = blockIdx.x * blockDim.x + threadIdx.x;   // float4 units
    if (idx >= N * 32) return;
    float4 v = ((const float4*)X)[idx];
    float4 hi, lo;
    hi.x = tf32f(v.x); lo.x = tf32f(v.x - hi.x);
    hi.y = tf32f(v.y); lo.y = tf32f(v.y - hi.y);
    hi.z = tf32f(v.z); lo.z = tf32f(v.z - hi.z);
    hi.w = tf32f(v.w); lo.w = tf32f(v.w - hi.w);
    ((float4*)g_xhi)[idx] = hi;
    ((float4*)g_xlo)[idx] = lo;
}

// ---------------- tensor-core TF32x3 GEMM: H = A @ B^T ----------------------
// A splits row-major [row][k]; B splits are W^T [n][k].
// Block: 256 threads = 8 warps as 4(m) x 2(n); block tile 64 x 128.
// Warp tile: m16 x n64 (8 n8-tiles), K loop in 8-steps, 3 mma per tile-step.
__global__ void __launch_bounds__(256)
k_gemm_tc(const float* __restrict__ Ahi, const float* __restrict__ Alo,
          const float* __restrict__ BThi, const float* __restrict__ BTlo,
          float* __restrict__ H, int N) {
    const int w    = threadIdx.x >> 5;
    const int lane = threadIdx.x & 31;
    const int g = lane >> 2, t = lane & 3;
    const int mi = w >> 1, nj = w & 1;

    const int rowA = blockIdx.x * 64 + mi * 16 + g;
    const int rowB = rowA + 8;
    const size_t aoff0 = (size_t)(rowA < N ? rowA : N - 1) * F;
    const size_t aoff1 = (size_t)(rowB < N ? rowB : N - 1) * F;
    const int col0 = nj * 64;

    const uint32_t* AH = (const uint32_t*)Ahi;
    const uint32_t* AL = (const uint32_t*)Alo;
    const uint32_t* BH = (const uint32_t*)BThi;
    const uint32_t* BL = (const uint32_t*)BTlo;

    float c[8][4];
#pragma unroll
    for (int nt = 0; nt < 8; nt++)
#pragma unroll
        for (int q = 0; q < 4; q++) c[nt][q] = 0.f;

#pragma unroll 2
    for (int k0 = 0; k0 < F; k0 += 8) {
        uint32_t ah0 = AH[aoff0 + k0 + t];
        uint32_t ah1 = AH[aoff1 + k0 + t];
        uint32_t ah2 = AH[aoff0 + k0 + t + 4];
        uint32_t ah3 = AH[aoff1 + k0 + t + 4];
        uint32_t al0 = AL[aoff0 + k0 + t];
        uint32_t al1 = AL[aoff1 + k0 + t];
        uint32_t al2 = AL[aoff0 + k0 + t + 4];
        uint32_t al3 = AL[aoff1 + k0 + t + 4];
#pragma unroll
        for (int nt = 0; nt < 8; nt++) {
            size_t boff = (size_t)(col0 + nt * 8 + g) * F + k0;
            uint32_t bh0 = BH[boff + t], bh1 = BH[boff + t + 4];
            uint32_t bl0 = BL[boff + t], bl1 = BL[boff + t + 4];
            mma_tf32(c[nt], ah0, ah1, ah2, ah3, bh0, bh1);   // hi*hi
            mma_tf32(c[nt], ah0, ah1, ah2, ah3, bl0, bl1);   // hi*lo
            mma_tf32(c[nt], al0, al1, al2, al3, bh0, bh1);   // lo*hi
        }
    }

#pragma unroll
    for (int nt = 0; nt < 8; nt++) {
        int col = col0 + nt * 8 + 2 * t;
        if (rowA < N)
            *(float2*)(H + (size_t)rowA * F + col) = make_float2(c[nt][0], c[nt][1]);
        if (rowB < N)
            *(float2*)(H + (size_t)rowB * F + col) = make_float2(c[nt][2], c[nt][3]);
    }
}

// ---------------- gather + self-loop + bias + LN + ReLU (device fn) ---------
__device__ __forceinline__ float4 gather_ln_node(
        const float* __restrict__ h, const float* __restrict__ b,
        const float* __restrict__ g, const float* __restrict__ be,
        int node, int lane) {
    const int beg = g_off[node];
    const int end = g_off[node + 1];

    float4 acc = make_float4(0.f, 0.f, 0.f, 0.f);

    int e = beg;
    for (; e + 4 <= end; e += 4) {
        int2 ew0 = g_ew[e];
        int2 ew1 = g_ew[e + 1];
        int2 ew2 = g_ew[e + 2];
        int2 ew3 = g_ew[e + 3];
        float4 h0 = ((const float4*)(h + (size_t)ew0.x * F))[lane];
        float4 h1 = ((const float4*)(h + (size_t)ew1.x * F))[lane];
        float4 h2 = ((const float4*)(h + (size_t)ew2.x * F))[lane];
        float4 h3 = ((const float4*)(h + (size_t)ew3.x * F))[lane];
        float w0 = __int_as_float(ew0.y), w1 = __int_as_float(ew1.y);
        float w2 = __int_as_float(ew2.y), w3 = __int_as_float(ew3.y);
        acc.x += h0.x * w0; acc.y += h0.y * w0; acc.z += h0.z * w0; acc.w += h0.w * w0;
        acc.x += h1.x * w1; acc.y += h1.y * w1; acc.z += h1.z * w1; acc.w += h1.w * w1;
        acc.x += h2.x * w2; acc.y += h2.y * w2; acc.z += h2.z * w2; acc.w += h2.w * w2;
        acc.x += h3.x * w3; acc.y += h3.y * w3; acc.z += h3.z * w3; acc.w += h3.w * w3;
    }
    for (; e < end; e++) {
        int2 ew0 = g_ew[e];
        float4 h0 = ((const float4*)(h + (size_t)ew0.x * F))[lane];
        float w0 = __int_as_float(ew0.y);
        acc.x += h0.x * w0; acc.y += h0.y * w0; acc.z += h0.z * w0; acc.w += h0.w * w0;
    }

    float di = g_dinv[node];
    float sn = di * di;
    float4 hs = ((const float4*)(h + (size_t)node * F))[lane];
    float4 bv = ((const float4*)b)[lane];
    acc.x += hs.x * sn + bv.x;
    acc.y += hs.y * sn + bv.y;
    acc.z += hs.z * sn + bv.z;
    acc.w += hs.w * sn + bv.w;

    float ssum = acc.x + acc.y + acc.z + acc.w;
#pragma unroll
    for (int o = 16; o; o >>= 1) ssum += __shfl_xor_sync(0xffffffffu, ssum, o);
    float mu = ssum * (1.0f / F);

    float4 dv;
    dv.x = acc.x - mu; dv.y = acc.y - mu; dv.z = acc.z - mu; dv.w = acc.w - mu;
    float ss = dv.x * dv.x + dv.y * dv.y + dv.z * dv.z + dv.w * dv.w;
#pragma unroll
    for (int o = 16; o; o >>= 1) ss += __shfl_xor_sync(0xffffffffu, ss, o);
    float rs = rsqrtf(ss * (1.0f / F) + LN_EPS);

    float4 gv  = ((const float4*)g)[lane];
    float4 bev = ((const float4*)be)[lane];
    float4 o4;
    o4.x = fmaxf(dv.x * rs * gv.x + bev.x, 0.f);
    o4.y = fmaxf(dv.y * rs * gv.y + bev.y, 0.f);
    o4.z = fmaxf(dv.z * rs * gv.z + bev.z, 0.f);
    o4.w = fmaxf(dv.w * rs * gv.w + bev.w, 0.f);
    return o4;
}

// gather variant writing tf32 hi/lo splits (feeds tensor-core GEMM2)
__global__ void __launch_bounds__(256)
k_gather_ln_split(const float* __restrict__ h,
                  const float* __restrict__ b, const float* __restrict__ g,
                  const float* __restrict__ be,
                  float* __restrict__ ohi, float* __restrict__ olo, int N) {
    int warp = (blockIdx.x * blockDim.x + threadIdx.x) >> 5;
    int lane = threadIdx.x & 31;
    if (warp >= N) return;
    float4 o4 = gather_ln_node(h, b, g, be, warp, lane);
    float4 hi, lo;
    hi.x = tf32f(o4.x); lo.x = tf32f(o4.x - hi.x);
    hi.y = tf32f(o4.y); lo.y = tf32f(o4.y - hi.y);
    hi.z = tf32f(o4.z); lo.z = tf32f(o4.z - hi.z);
    hi.w = tf32f(o4.w); lo.w = tf32f(o4.w - hi.w);
    ((float4*)(ohi + (size_t)warp * F))[lane] = hi;
    ((float4*)(olo + (size_t)warp * F))[lane] = lo;
}

// plain gather (final output)
__global__ void __launch_bounds__(256)
k_gather_ln(const float* __restrict__ h,
            const float* __restrict__ b, const float* __restrict__ g,
            const float* __restrict__ be, float* __restrict__ out, int N) {
    int warp = (blockIdx.x * blockDim.x + threadIdx.x) >> 5;
    int lane = threadIdx.x & 31;
    if (warp >= N) return;
    float4 o4 = gather_ln_node(h, b, g, be, warp, lane);
    ((float4*)(out + (size_t)warp * F))[lane] = o4;
}

// ---------------- launch ----------------------------------------------------
extern "C" void kernel_launch(void* const* d_in, const int* in_sizes, int n_in,
                              void* d_out, int out_size) {
    const float* x   = (const float*)d_in[0];
    const void*  ei  = d_in[1];
    const float* W1  = (const float*)d_in[2];
    const float* b1  = (const float*)d_in[3];
    const float* g1  = (const float*)d_in[4];
    const float* be1 = (const float*)d_in[5];
    const float* W2  = (const float*)d_in[6];
    const float* b2  = (const float*)d_in[7];
    const float* g2  = (const float*)d_in[8];
    const float* be2 = (const float*)d_in[9];
    float* out = (float*)d_out;

    const int N = in_sizes[0] / F;
    const int E = in_sizes[1] / 2;

    float *h, *h3, *xhi, *xlo, *h2hi, *h2lo, *w1hi, *w1lo, *w2hi, *w2lo;
    int   *degi;
    cudaGetSymbolAddress((void**)&h,    g_h);
    cudaGetSymbolAddress((void**)&h3,   g_h3);
    cudaGetSymbolAddress((void**)&xhi,  g_xhi);
    cudaGetSymbolAddress((void**)&xlo,  g_xlo);
    cudaGetSymbolAddress((void**)&h2hi, g_h2hi);
    cudaGetSymbolAddress((void**)&h2lo, g_h2lo);
    cudaGetSymbolAddress((void**)&w1hi, g_w1hi);
    cudaGetSymbolAddress((void**)&w1lo, g_w1lo);
    cudaGetSymbolAddress((void**)&w2hi, g_w2hi);
    cudaGetSymbolAddress((void**)&w2lo, g_w2lo);
    cudaGetSymbolAddress((void**)&degi, g_degi);

    const int nbN  = (N + 255) / 256;
    const int nbE  = (E + 255) / 256;
    const int nbW  = (N * 32 + 255) / 256;     // warp per node
    const int nbS  = (N + 4095) / 4096;        // scan phase-1 blocks
    const int nbX  = (N * 32 + 255) / 256;     // split-x
    const int nbWS = (2 * F * F + 255) / 256;  // split-w
    const int nbTC = (N + 63) / 64;            // GEMM blocks

    // streams/events: CSR + W-split on s2, main chain on s0.
    cudaStream_t s2;
    cudaEvent_t ev_fork, ev_w, ev_join;
    cudaStreamCreateWithFlags(&s2, cudaStreamNonBlocking);
    cudaEventCreateWithFlags(&ev_fork, cudaEventDisableTiming);
    cudaEventCreateWithFlags(&ev_w,    cudaEventDisableTiming);
    cudaEventCreateWithFlags(&ev_join, cudaEventDisableTiming);

    cudaEventRecord(ev_fork, 0);
    cudaStreamWaitEvent(s2, ev_fork, 0);

    k_split_w<<<nbWS, 256, 0, s2>>>(W1, W2);
    cudaEventRecord(ev_w, s2);
    cudaMemsetAsync(degi, 0, (size_t)N * sizeof(int), s2);
    k_convert_count<<<nbE, 256, 0, s2>>>(ei, N, E);
    k_scan1<<<nbS, 1024, 0, s2>>>(N);
    k_scan3<<<nbN, 256, 0, s2>>>(N, nbS);
    k_fill<<<nbE, 256, 0, s2>>>(E);
    cudaEventRecord(ev_join, s2);

    // s0: split X, then tensor-core GEMM1 (needs W split)
    k_split_x<<<nbX, 256>>>(x, N);
    cudaStreamWaitEvent(0, ev_w, 0);
    k_gemm_tc<<<nbTC, 256>>>(xhi, xlo, w1hi, w1lo, h, N);

    cudaStreamWaitEvent(0, ev_join, 0);

    // gather1 + LN -> split output (feeds GEMM2 directly)
    k_gather_ln_split<<<nbW, 256>>>(h, b1, g1, be1, h2hi, h2lo, N);

    // GEMM2 on tensor cores
    k_gemm_tc<<<nbTC, 256>>>(h2hi, h2lo, w2hi, w2lo, h3, N);

    // final gather + LN
    k_gather_ln<<<nbW, 256>>>(h3, b2, g2, be2, out, N);
}

// round 17
// speedup vs baseline: 1.9273x; 1.9273x over previous
#include <cuda_runtime.h>
#include <cstdint>

#define MAXN 50000
#define MAXE 600064
#define F 128
#define LN_EPS 1e-5f

// ---------------- scratch (device globals; no allocation allowed) ----------
__device__ int   g_src[MAXE];
__device__ int   g_dst[MAXE];
__device__ float g_dinv[MAXN];
__device__ int   g_degi[MAXN];
__device__ int   g_off[MAXN + 1];
__device__ int   g_cur[MAXN];
__device__ int2  g_ew[MAXE];      // packed {src, weight bits}
__device__ float g_h[MAXN * F];
__device__ float g_h2[MAXN * F];
__device__ int   g_bsum[16];

// -------- convert edges (dtype-probing) + degree count ----------------------
__global__ void k_convert_count(const void* __restrict__ ei_raw, int N, int E) {
    __shared__ int s_is64;
    if (threadIdx.x == 0) {
        const unsigned long long* p = (const unsigned long long*)ei_raw;
        unsigned long long mx = 0;
#pragma unroll
        for (int i = 0; i < 32; i++) mx = mx > p[i] ? mx : p[i];
        s_is64 = (mx < (unsigned long long)N);
    }
    __syncthreads();
    int e = blockIdx.x * blockDim.x + threadIdx.x;
    if (e >= E) return;
    int s, d;
    if (s_is64) {
        const long long* p = (const long long*)ei_raw;
        s = (int)p[e]; d = (int)p[E + e];
    } else {
        const int* p = (const int*)ei_raw;
        s = p[e]; d = p[E + e];
    }
    g_src[e] = s;
    g_dst[e] = d;
    atomicAdd(&g_degi[d], 1);
}

// ---------------- scan phase 1: per-block exclusive scan (4096/block) -------
__global__ void __launch_bounds__(1024)
k_scan1(int n) {
    __shared__ int sh[32];
    const int lane = threadIdx.x & 31;
    const int wid  = threadIdx.x >> 5;
    const int i0 = blockIdx.x * 4096 + threadIdx.x * 4;

    int v0 = (i0 + 0 < n) ? g_degi[i0 + 0] : 0;
    int v1 = (i0 + 1 < n) ? g_degi[i0 + 1] : 0;
    int v2 = (i0 + 2 < n) ? g_degi[i0 + 2] : 0;
    int v3 = (i0 + 3 < n) ? g_degi[i0 + 3] : 0;
    int s = v0 + v1 + v2 + v3;

    int x = s;
#pragma unroll
    for (int o = 1; o < 32; o <<= 1) {
        int y = __shfl_up_sync(0xffffffffu, x, o);
        if (lane >= o) x += y;
    }
    if (lane == 31) sh[wid] = x;
    __syncthreads();
    if (wid == 0) {
        int t = sh[lane];
#pragma unroll
        for (int o = 1; o < 32; o <<= 1) {
            int y = __shfl_up_sync(0xffffffffu, t, o);
            if (lane >= o) t += y;
        }
        sh[lane] = t;
    }
    __syncthreads();
    int excl = x - s + ((wid == 0) ? 0 : sh[wid - 1]);

    if (i0 + 0 < n) g_off[i0 + 0] = excl;
    if (i0 + 1 < n) g_off[i0 + 1] = excl + v0;
    if (i0 + 2 < n) g_off[i0 + 2] = excl + v0 + v1;
    if (i0 + 3 < n) g_off[i0 + 3] = excl + v0 + v1 + v2;
    if (threadIdx.x == 1023) g_bsum[blockIdx.x] = excl + s;
}

// ------- scan phase 2 (fused): add block offsets, init cur & dinv ------------
__global__ void k_scan3(int n, int nblk) {
    __shared__ int s_boff;
    int grp = (blockIdx.x * blockDim.x) >> 12;
    if (threadIdx.x == 0) {
        int s = 0;
        for (int b = 0; b < grp; b++) s += g_bsum[b];
        s_boff = s;
    }
    __syncthreads();
    int i = blockIdx.x * blockDim.x + threadIdx.x;
    if (i < n) {
        int val = g_off[i] + s_boff;
        g_off[i] = val;
        g_cur[i] = val;
        g_dinv[i] = rsqrtf((float)g_degi[i] + 1.0f);
    }
    if (blockIdx.x == 0 && threadIdx.x == 0) {
        int s = 0;
        for (int b = 0; b < nblk; b++) s += g_bsum[b];
        g_off[n] = s;
    }
}

__global__ void k_fill(int E) {
    int e = blockIdx.x * blockDim.x + threadIdx.x;
    if (e >= E) return;
    int s = g_src[e];
    int d = g_dst[e];
    int pos = atomicAdd(&g_cur[d], 1);
    float w = g_dinv[s] * g_dinv[d];
    g_ew[pos] = make_int2(s, __float_as_int(w));
}

// ---------------- SGEMM: H[N,128] = X[N,128] @ W[128,128] ------------------
// FFMA2 path, R5/R8-measured geometry (8 rows x 4 cols per thread).
// NEW vs R13: __launch_bounds__(256, 3) -> 3 CTAs/SM (192KB smem of 228KB),
// 782-block grid runs in 2 waves instead of 3.
#define GST 256

__global__ void __launch_bounds__(256, 3)
k_gemm128(const float* __restrict__ X, const float* __restrict__ W,
          float* __restrict__ H, int N) {
    extern __shared__ float xs[];   // 64 * GST floats = 64KB

    const int row0 = blockIdx.x * 64;
    const int c  = threadIdx.x & 31;
    const int rg = threadIdx.x >> 5;

    // stage + duplicate
    for (int i = threadIdx.x; i < 64 * 32; i += 256) {
        int r  = i >> 5;
        int k4 = i & 31;
        float4 v = make_float4(0.f, 0.f, 0.f, 0.f);
        int row = row0 + r;
        if (row < N)
            v = ((const float4*)(X + (size_t)row * F))[k4];
        float* p = &xs[r * GST + k4 * 8];
        *(float4*)(p)     = make_float4(v.x, v.x, v.y, v.y);
        *(float4*)(p + 4) = make_float4(v.z, v.z, v.w, v.w);
    }
    __syncthreads();

    unsigned long long acc[8][2];
#pragma unroll
    for (int r = 0; r < 8; r++) { acc[r][0] = 0ULL; acc[r][1] = 0ULL; }

    const float* Wc = W + 4 * c;
    const float* xbase = &xs[(rg * 8) * GST];

#pragma unroll 8
    for (int k = 0; k < 128; k++) {
        ulonglong2 w2 = *(const ulonglong2*)(Wc + k * F);
#pragma unroll
        for (int r = 0; r < 8; r++) {
            unsigned long long xd =
                *(const unsigned long long*)(xbase + r * GST + 2 * k);
            asm("fma.rn.f32x2 %0, %1, %2, %0;" : "+l"(acc[r][0]) : "l"(xd), "l"(w2.x));
            asm("fma.rn.f32x2 %0, %1, %2, %0;" : "+l"(acc[r][1]) : "l"(xd), "l"(w2.y));
        }
    }

#pragma unroll
    for (int r = 0; r < 8; r++) {
        int row = row0 + rg * 8 + r;
        if (row < N) {
            float o0, o1, o2, o3;
            asm("mov.b64 {%0, %1}, %2;" : "=f"(o0), "=f"(o1) : "l"(acc[r][0]));
            asm("mov.b64 {%0, %1}, %2;" : "=f"(o2), "=f"(o3) : "l"(acc[r][1]));
            ((float4*)(H + (size_t)row * F))[c] = make_float4(o0, o1, o2, o3);
        }
    }
}

// ------- fused gather + self-loop + bias + LayerNorm + ReLU -----------------
// one warp per node; edge loop unrolled x2 (MLP=2). (R13-measured best.)
__global__ void __launch_bounds__(256)
k_gather_ln(const float* __restrict__ h,
            const float* __restrict__ b, const float* __restrict__ g,
            const float* __restrict__ be, float* __restrict__ out, int N) {
    int warp = (blockIdx.x * blockDim.x + threadIdx.x) >> 5;
    int lane = threadIdx.x & 31;
    if (warp >= N) return;

    const int beg = g_off[warp];
    const int end = g_off[warp + 1];

    float4 acc = make_float4(0.f, 0.f, 0.f, 0.f);

    int e = beg;
    for (; e + 2 <= end; e += 2) {
        int2 ew0 = g_ew[e];
        int2 ew1 = g_ew[e + 1];
        float4 h0 = ((const float4*)(h + (size_t)ew0.x * F))[lane];
        float4 h1 = ((const float4*)(h + (size_t)ew1.x * F))[lane];
        float w0 = __int_as_float(ew0.y);
        float w1 = __int_as_float(ew1.y);
        acc.x += h0.x * w0; acc.y += h0.y * w0;
        acc.z += h0.z * w0; acc.w += h0.w * w0;
        acc.x += h1.x * w1; acc.y += h1.y * w1;
        acc.z += h1.z * w1; acc.w += h1.w * w1;
    }
    if (e < end) {
        int2 ew0 = g_ew[e];
        float4 h0 = ((const float4*)(h + (size_t)ew0.x * F))[lane];
        float w0 = __int_as_float(ew0.y);
        acc.x += h0.x * w0; acc.y += h0.y * w0;
        acc.z += h0.z * w0; acc.w += h0.w * w0;
    }

    // self-loop + bias
    float di = g_dinv[warp];
    float sn = di * di;
    float4 hs = ((const float4*)(h + (size_t)warp * F))[lane];
    float4 bv = ((const float4*)b)[lane];
    acc.x += hs.x * sn + bv.x;
    acc.y += hs.y * sn + bv.y;
    acc.z += hs.z * sn + bv.z;
    acc.w += hs.w * sn + bv.w;

    // LayerNorm
    float ssum = acc.x + acc.y + acc.z + acc.w;
#pragma unroll
    for (int o = 16; o; o >>= 1) ssum += __shfl_xor_sync(0xffffffffu, ssum, o);
    float mu = ssum * (1.0f / F);

    float4 dv;
    dv.x = acc.x - mu; dv.y = acc.y - mu; dv.z = acc.z - mu; dv.w = acc.w - mu;
    float ss = dv.x * dv.x + dv.y * dv.y + dv.z * dv.z + dv.w * dv.w;
#pragma unroll
    for (int o = 16; o; o >>= 1) ss += __shfl_xor_sync(0xffffffffu, ss, o);
    float rs = rsqrtf(ss * (1.0f / F) + LN_EPS);

    float4 gv  = ((const float4*)g)[lane];
    float4 bev = ((const float4*)be)[lane];
    float4 o4;
    o4.x = fmaxf(dv.x * rs * gv.x + bev.x, 0.f);
    o4.y = fmaxf(dv.y * rs * gv.y + bev.y, 0.f);
    o4.z = fmaxf(dv.z * rs * gv.z + bev.z, 0.f);
    o4.w = fmaxf(dv.w * rs * gv.w + bev.w, 0.f);
    ((float4*)(out + (size_t)warp * F))[lane] = o4;
}

// ---------------- launch ----------------------------------------------------
extern "C" void kernel_launch(void* const* d_in, const int* in_sizes, int n_in,
                              void* d_out, int out_size) {
    const float* x   = (const float*)d_in[0];
    const void*  ei  = d_in[1];
    const float* W1  = (const float*)d_in[2];
    const float* b1  = (const float*)d_in[3];
    const float* g1  = (const float*)d_in[4];
    const float* be1 = (const float*)d_in[5];
    const float* W2  = (const float*)d_in[6];
    const float* b2  = (const float*)d_in[7];
    const float* g2  = (const float*)d_in[8];
    const float* be2 = (const float*)d_in[9];
    float* out = (float*)d_out;

    const int N = in_sizes[0] / F;
    const int E = in_sizes[1] / 2;

    float *h, *h2;
    int   *degi;
    cudaGetSymbolAddress((void**)&h,    g_h);
    cudaGetSymbolAddress((void**)&h2,   g_h2);
    cudaGetSymbolAddress((void**)&degi, g_degi);

    const int GEMM_SMEM = 64 * GST * (int)sizeof(float);
    cudaFuncSetAttribute(k_gemm128,
                         cudaFuncAttributeMaxDynamicSharedMemorySize, GEMM_SMEM);

    const int nbN = (N + 255) / 256;
    const int nbE = (E + 255) / 256;
    const int nbG = (N + 63) / 64;
    const int nbW = (N * 32 + 255) / 256;
    const int nbS = (N + 4095) / 4096;

    // R10/R13 coarse fork-join schedule (measured best): CSR on s2 || GEMM1.
    cudaStream_t s2;
    cudaEvent_t ev_fork, ev_join;
    cudaStreamCreateWithFlags(&s2, cudaStreamNonBlocking);
    cudaEventCreateWithFlags(&ev_fork, cudaEventDisableTiming);
    cudaEventCreateWithFlags(&ev_join, cudaEventDisableTiming);

    cudaEventRecord(ev_fork, 0);
    cudaStreamWaitEvent(s2, ev_fork, 0);

    cudaMemsetAsync(degi, 0, (size_t)N * sizeof(int), s2);
    k_convert_count<<<nbE, 256, 0, s2>>>(ei, N, E);
    k_scan1<<<nbS, 1024, 0, s2>>>(N);
    k_scan3<<<nbN, 256, 0, s2>>>(N, nbS);
    k_fill<<<nbE, 256, 0, s2>>>(E);
    cudaEventRecord(ev_join, s2);

    k_gemm128<<<nbG, 256, GEMM_SMEM>>>(x, W1, h, N);   // stream 0

    cudaStreamWaitEvent(0, ev_join, 0);

    k_gather_ln<<<nbW, 256>>>(h, b1, g1, be1, h2, N);

    // ---- layer 2 (serial chain on stream 0) ----
    k_gemm128<<<nbG, 256, GEMM_SMEM>>>(h2, W2, h, N);
    k_gather_ln<<<nbW, 256>>>(h, b2, g2, be2, out, N);
}